// round 15
// baseline (speedup 1.0000x reference)
#include <cuda_runtime.h>
#include <cuda_fp16.h>
#include <math.h>
#include <stdint.h>

// Problem constants
#define BN 4
#define CN 64
#define HN 128
#define WN 128
#define ON 64
#define K2C 9
#define HW (HN*WN)
#define CK 576          // CN * K2C

typedef unsigned long long ull;

// ---------------- scratch ----------------
__device__ __align__(16) float    g_sy[BN*K2C*HW];   // sample y coords
__device__ __align__(16) float    g_sx[BN*K2C*HW];   // sample x coords
__device__ __align__(16) float    g_mm[BN*HW];       // mean sigmoid modulation
__device__ __align__(16) __half   g_wh[K2C*ON*CN];   // main weight f16 [tap][o][c]
__device__ __align__(16) uint32_t g_wsA[K2C*32*36];  // offset+mod weight f16 pairs [tap][32ch][36]
__device__ __align__(16) __half   g_xT[BN*HW*CN];    // x transposed, channel-last f16 [b][h*w][c]

// ---------------- mma.sync m16n8k16 f16->f32 (base PTX, works on sm_103) ----------------
__device__ __forceinline__ void mma16816(float* d,
                                         uint32_t a0, uint32_t a1, uint32_t a2, uint32_t a3,
                                         uint32_t b0, uint32_t b1){
  asm volatile(
    "mma.sync.aligned.m16n8k16.row.col.f32.f16.f16.f32 "
    "{%0,%1,%2,%3}, {%4,%5,%6,%7}, {%8,%9}, {%0,%1,%2,%3};"
    : "+f"(d[0]), "+f"(d[1]), "+f"(d[2]), "+f"(d[3])
    : "r"(a0), "r"(a1), "r"(a2), "r"(a3), "r"(b0), "r"(b1));
}

// ---------------- kernel T+B fused: transpose x AND weight prep ----------------
__global__ __launch_bounds__(256)
void prep_all(const float* __restrict__ x,
              const float* __restrict__ weight,
              const float* __restrict__ offw,
              const float* __restrict__ modw){
  const int bx = blockIdx.x;
  if (bx < HN*BN){
    // ---- transpose x -> channel-last f16 (float4 loads, 4x fewer instrs) ----
    __shared__ uint32_t T[128*36];   // [px][36 u32]
    const int b  = bx >> 7;
    const int ho = bx & 127;
    const float* xr = x + b*CN*HW + ho*WN;

    // 32 channel-pairs x 32 px-quads = 1024 tasks, 4 per thread
    for (int j = threadIdx.x; j < 32*32; j += 256){
      int cp = j >> 5;          // channel pair 0..31
      int q  = j & 31;          // px quad 0..31
      float4 v0 = *(const float4*)(xr + (2*cp    )*HW + q*4);
      float4 v1 = *(const float4*)(xr + (2*cp + 1)*HW + q*4);
      __half2 h0 = __floats2half2_rn(v0.x, v1.x);
      __half2 h1 = __floats2half2_rn(v0.y, v1.y);
      __half2 h2 = __floats2half2_rn(v0.z, v1.z);
      __half2 h3 = __floats2half2_rn(v0.w, v1.w);
      T[(q*4    )*36 + cp] = *(uint32_t*)&h0;
      T[(q*4 + 1)*36 + cp] = *(uint32_t*)&h1;
      T[(q*4 + 2)*36 + cp] = *(uint32_t*)&h2;
      T[(q*4 + 3)*36 + cp] = *(uint32_t*)&h3;
    }
    __syncthreads();

    float4* dst = (float4*)(g_xT + (b*HW + ho*WN)*CN);
    for (int j = threadIdx.x; j < 128*8; j += 256){
      int px = j >> 3, f4 = j & 7;
      dst[j] = *(float4*)&T[px*36 + f4*4];
    }
  } else {
    // ---- weight prep ----
    int i = (bx - HN*BN)*256 + threadIdx.x;
    if (i < K2C*ON*CN){
      int c = i & 63, o = (i >> 6) & 63, k = i >> 12;
      g_wh[i] = __float2half(weight[(o*CN + c)*K2C + k]);
    }
    if (i < K2C*32*32){
      int tap = i >> 10;
      int rem = i & 1023;
      int ch  = rem >> 5;
      int cp  = rem & 31;
      float v0 = 0.f, v1 = 0.f;
      int c0 = cp*2, c1 = cp*2 + 1;
      if (ch < 18){
        v0 = offw[ch*CK + c0*9 + tap];
        v1 = offw[ch*CK + c1*9 + tap];
      } else if (ch < 27){
        v0 = modw[(ch-18)*CK + c0*9 + tap];
        v1 = modw[(ch-18)*CK + c1*9 + tap];
      }
      __half2 h2 = __floats2half2_rn(v0, v1);
      g_wsA[(tap*32 + ch)*36 + cp] = *(uint32_t*)&h2;
    }
    if (i < K2C*32*4){
      int row = i >> 2, cp = 32 + (i & 3);
      g_wsA[row*36 + cp] = 0u;
    }
  }
}

// ---------------- kernel A: offset + modulation conv via HMMA (unchanged) ----------------
#define XSP 72
#define XS_HALVES (3*130*XSP)            // 28080
#define WS_U32   (K2C*32*36)             // 10368
#define OSM_BYTES (XS_HALVES*2 + WS_U32*4)   // 97632 B

__device__ __forceinline__ void write_pix(int b, int ho, int wo,
                                          const float* __restrict__ offb,
                                          const float* __restrict__ modb,
                                          const float (&rr)[28]){
  float msum = 0.f;
  #pragma unroll
  for (int k = 0; k < 9; k++){
    float kyf = (float)(k/3) - 1.f;
    float kxf = (float)(k%3) - 1.f;
    int idx = ((b*9 + k)*HN + ho)*WN + wo;
    g_sy[idx] = (float)ho + kyf + rr[k]     + offb[k];
    g_sx[idx] = (float)wo + kxf + rr[9 + k] + offb[9 + k];
    float z = rr[18 + k] + modb[k];
    msum += 1.f / (1.f + expf(-z));
  }
  g_mm[(b*HN + ho)*WN + wo] = msum * (1.f/9.f);
}

__global__ __launch_bounds__(256, 2)
void offset_mma(const float* __restrict__ offb,
                const float* __restrict__ modb){
  extern __shared__ char osm[];
  __half*   Xs  = (__half*)osm;                    // [3*130][72]
  uint32_t* Ws  = (uint32_t*)(osm + XS_HALVES*2);  // [288][36]
  float*    Dsm = (float*)osm;                     // [128][33] (aliases Xs after sync)

  const int tid  = threadIdx.x;
  const int lane = tid & 31;
  const int wp   = tid >> 5;
  const int g    = lane >> 2;
  const int tg   = lane & 3;
  const int b    = blockIdx.y;
  const int ho   = blockIdx.x;

  {
    const float4* src = (const float4*)g_wsA;
    float4* dst = (float4*)Ws;
    for (int i = tid; i < WS_U32/4; i += 256) dst[i] = src[i];
  }

  {
    const int f4 = tid & 7;
    const uint4 zero4 = make_uint4(0,0,0,0);
    const __half* xtb = g_xT + b*HW*CN;
    for (int pos = tid >> 3; pos < 390; pos += 32){
      int r    = (pos >= 260) ? 2 : (pos >= 130 ? 1 : 0);
      int px_i = pos - r*130;
      int row  = ho - 1 + r;
      int wo   = px_i - 1;
      bool ok  = (row >= 0) && (row < HN) && (wo >= 0) && (wo < WN);
      uint4 v = ok ? *(const uint4*)(xtb + (row*WN + wo)*CN + f4*8) : zero4;
      *(uint4*)(Xs + pos*XSP + f4*8) = v;
    }
  }
  __syncthreads();

  float acc[4][4];
  #pragma unroll
  for (int nt = 0; nt < 4; nt++)
    #pragma unroll
    for (int j = 0; j < 4; j++) acc[nt][j] = 0.f;

  #pragma unroll
  for (int t = 0; t < 9; t++){
    const int ky = t / 3, kx = t % 3;
    const __half* Ar0 = Xs + (ky*130 + wp*16 + g + kx)*XSP;
    const __half* Ar1 = Ar0 + 8*XSP;
    const uint32_t* Wt = Ws + (t*32)*36;
    #pragma unroll
    for (int kt = 0; kt < 4; kt++){
      const int k0 = kt*16 + tg*2;
      uint32_t a0 = *(const uint32_t*)(Ar0 + k0);
      uint32_t a1 = *(const uint32_t*)(Ar1 + k0);
      uint32_t a2 = *(const uint32_t*)(Ar0 + k0 + 8);
      uint32_t a3 = *(const uint32_t*)(Ar1 + k0 + 8);
      #pragma unroll
      for (int nt = 0; nt < 4; nt++){
        const uint32_t* Wr = Wt + (nt*8 + g)*36 + (k0 >> 1);
        uint32_t b0 = Wr[0];
        uint32_t b1 = Wr[4];
        mma16816(acc[nt], a0, a1, a2, a3, b0, b1);
      }
    }
  }
  __syncthreads();

  {
    const int px0 = wp*16 + g;
    const int px1 = px0 + 8;
    #pragma unroll
    for (int nt = 0; nt < 4; nt++){
      int ch = nt*8 + tg*2;
      Dsm[px0*33 + ch]     = acc[nt][0];
      Dsm[px0*33 + ch + 1] = acc[nt][1];
      Dsm[px1*33 + ch]     = acc[nt][2];
      Dsm[px1*33 + ch + 1] = acc[nt][3];
    }
  }
  __syncthreads();

  if (tid < 128){
    float rr[28];
    #pragma unroll
    for (int j = 0; j < 28; j++) rr[j] = Dsm[tid*33 + j];
    write_pix(b, ho, tid, offb, modb, rr);
  }
}

// ---------------- kernel C: double-buffered sample + HMMA, one sync/tap (unchanged) ----------------
#define APAD 72
#define ASZ (128*APAD)      // halves per A buffer
#define WSZ (ON*APAD)       // halves per W buffer
#define DSM2 ((2*ASZ + 2*WSZ)*2)   // 55296 bytes

__device__ __forceinline__ void sample_tap(int b, int t, int ho, int wp, int pxo,
                                           const __half* __restrict__ xtb, int co,
                                           __half* __restrict__ An){
  #pragma unroll
  for (int it = 0; it < 4; it++){
    const int px = wp*16 + it*4 + pxo;
    const int sidx = ((b*9 + t)*HN + ho)*WN + px;
    float sy = g_sy[sidx], sx = g_sx[sidx];
    float y0f = floorf(sy), x0f = floorf(sx);
    float wy1 = sy - y0f, wx1 = sx - x0f;
    float wy0 = 1.f - wy1, wx0 = 1.f - wx1;
    int y0 = (int)y0f, x0i = (int)x0f;
    int y1 = y0 + 1,  x1i = x0i + 1;
    float my0 = (y0  >= 0 && y0  < HN) ? 1.f : 0.f;
    float my1 = (y1  >= 0 && y1  < HN) ? 1.f : 0.f;
    float mx0 = (x0i >= 0 && x0i < WN) ? 1.f : 0.f;
    float mx1 = (x1i >= 0 && x1i < WN) ? 1.f : 0.f;
    int cy0 = min(max(y0, 0), HN-1),  cy1 = min(max(y1, 0), HN-1);
    int cx0 = min(max(x0i, 0), WN-1), cx1 = min(max(x1i, 0), WN-1);
    __half2 W00 = __float2half2_rn(wy0*wx0*my0*mx0);
    __half2 W01 = __float2half2_rn(wy0*wx1*my0*mx1);
    __half2 W10 = __float2half2_rn(wy1*wx0*my1*mx0);
    __half2 W11 = __float2half2_rn(wy1*wx1*my1*mx1);

    uint4 c00 = *(const uint4*)(xtb + (cy0*WN + cx0)*CN + co);
    uint4 c01 = *(const uint4*)(xtb + (cy0*WN + cx1)*CN + co);
    uint4 c10 = *(const uint4*)(xtb + (cy1*WN + cx0)*CN + co);
    uint4 c11 = *(const uint4*)(xtb + (cy1*WN + cx1)*CN + co);

    const __half2* h00 = (const __half2*)&c00;
    const __half2* h01 = (const __half2*)&c01;
    const __half2* h10 = (const __half2*)&c10;
    const __half2* h11 = (const __half2*)&c11;
    __half2 s[4];
    #pragma unroll
    for (int j = 0; j < 4; j++){
      __half2 a = __hmul2(W00, h00[j]);
      a = __hfma2(W01, h01[j], a);
      a = __hfma2(W10, h10[j], a);
      a = __hfma2(W11, h11[j], a);
      s[j] = a;
    }
    *(uint4*)&An[px*APAD + co] = *(uint4*)s;
  }
}

__global__ __launch_bounds__(256, 2)
void deform_mma(const float* __restrict__ bias,
                float* __restrict__ out){
  extern __shared__ __half dsm2[];
  __half* Asm = dsm2;            // [2][128][APAD]
  __half* Wsm = dsm2 + 2*ASZ;    // [2][64][APAD]

  const int tid   = threadIdx.x;
  const int lane  = tid & 31;
  const int wp    = tid >> 5;
  const int g     = lane >> 2;
  const int tg    = lane & 3;
  const int pxo   = lane >> 3;
  const int chunk = lane & 7;
  const int b     = blockIdx.y;
  const int ho    = blockIdx.x;
  const __half* xtb = g_xT + b*HW*CN;
  const int co = chunk*8;

  float acc[8][4];
  #pragma unroll
  for (int nt = 0; nt < 8; nt++)
    #pragma unroll
    for (int j = 0; j < 4; j++) acc[nt][j] = 0.f;

  // ---- prologue: tap 0 into buffer 0 ----
  {
    const uint32_t* src = (const uint32_t*)g_wh;
    uint32_t* dst = (uint32_t*)Wsm;
    #pragma unroll
    for (int r = 0; r < 8; r++){
      int j = tid + r*256;
      dst[(j >> 5)*(APAD/2) + (j & 31)] = src[j];
    }
    sample_tap(b, 0, ho, wp, pxo, xtb, co, Asm);
  }
  __syncthreads();

  // ---- taps: stage W(t+1) + sample(t+1) into nxt, HMMA on cur, ONE sync ----
  for (int t = 0; t < 9; t++){
    const int cur = t & 1;
    const __half* Ac = Asm + cur*ASZ;
    const __half* Wc = Wsm + cur*WSZ;

    if (t < 8){
      __half* An = Asm + (cur^1)*ASZ;
      uint32_t* Wn = (uint32_t*)(Wsm + (cur^1)*WSZ);
      const uint32_t* src = (const uint32_t*)(g_wh + (t+1)*ON*CN);
      #pragma unroll
      for (int r = 0; r < 8; r++){
        int j = tid + r*256;
        Wn[(j >> 5)*(APAD/2) + (j & 31)] = src[j];
      }
      sample_tap(b, t+1, ho, wp, pxo, xtb, co, An);
    }

    // HMMA: warp m16 x n64 x k64 on cur
    const __half* Ar0 = Ac + (wp*16 + g)*APAD;
    const __half* Ar1 = Ar0 + 8*APAD;
    #pragma unroll
    for (int kt = 0; kt < 4; kt++){
      const int k0 = kt*16 + tg*2;
      uint32_t a0 = *(const uint32_t*)(Ar0 + k0);
      uint32_t a1 = *(const uint32_t*)(Ar1 + k0);
      uint32_t a2 = *(const uint32_t*)(Ar0 + k0 + 8);
      uint32_t a3 = *(const uint32_t*)(Ar1 + k0 + 8);
      #pragma unroll
      for (int nt = 0; nt < 8; nt++){
        const __half* Wr = Wc + (nt*8 + g)*APAD + k0;
        uint32_t b0 = *(const uint32_t*)(Wr);
        uint32_t b1 = *(const uint32_t*)(Wr + 8);
        mma16816(acc[nt], a0, a1, a2, a3, b0, b1);
      }
    }
    __syncthreads();
  }

  // ---- epilogue: * mod_mean + bias ----
  const int px0 = wp*16 + g;
  const int px1 = px0 + 8;
  const float mm0 = g_mm[(b*HN + ho)*WN + px0];
  const float mm1 = g_mm[(b*HN + ho)*WN + px1];
  #pragma unroll
  for (int nt = 0; nt < 8; nt++){
    int o0 = nt*8 + tg*2;
    float b0 = bias[o0], b1 = bias[o0 + 1];
    float* o0p = out + ((b*ON + o0    )*HN + ho)*WN;
    float* o1p = out + ((b*ON + o0 + 1)*HN + ho)*WN;
    o0p[px0] = acc[nt][0]*mm0 + b0;
    o1p[px0] = acc[nt][1]*mm0 + b1;
    o0p[px1] = acc[nt][2]*mm1 + b0;
    o1p[px1] = acc[nt][3]*mm1 + b1;
  }
}

// ---------------- launch ----------------
extern "C" void kernel_launch(void* const* d_in, const int* in_sizes, int n_in,
                              void* d_out, int out_size) {
  const float* x      = (const float*)d_in[0];
  const float* weight = (const float*)d_in[1];
  const float* bias   = (const float*)d_in[2];
  const float* offw   = (const float*)d_in[3];
  const float* offb   = (const float*)d_in[4];
  const float* modw   = (const float*)d_in[5];
  const float* modb   = (const float*)d_in[6];
  float* out = (float*)d_out;

  cudaFuncSetAttribute(offset_mma, cudaFuncAttributeMaxDynamicSharedMemorySize, OSM_BYTES);
  cudaFuncSetAttribute(deform_mma, cudaFuncAttributeMaxDynamicSharedMemorySize, DSM2);

  prep_all<<<HN*BN + 144, 256>>>(x, weight, offw, modw);
  offset_mma<<<dim3(HN, BN), 256, OSM_BYTES>>>(offb, modb);
  deform_mma<<<dim3(HN, BN), 256, DSM2>>>(bias, out);
}

// round 16
// speedup vs baseline: 1.0567x; 1.0567x over previous
#include <cuda_runtime.h>
#include <cuda_fp16.h>
#include <math.h>
#include <stdint.h>

// Problem constants
#define BN 4
#define CN 64
#define HN 128
#define WN 128
#define ON 64
#define K2C 9
#define HW (HN*WN)
#define CK 576          // CN * K2C

typedef unsigned long long ull;

// ---------------- scratch ----------------
__device__ __align__(16) float    g_sy[BN*K2C*HW];   // sample y coords
__device__ __align__(16) float    g_sx[BN*K2C*HW];   // sample x coords
__device__ __align__(16) float    g_mm[BN*HW];       // mean sigmoid modulation
__device__ __align__(16) __half   g_wh[K2C*ON*CN];   // main weight f16 [tap][o][c]
__device__ __align__(16) uint32_t g_wsA[K2C*32*36];  // offset+mod weight f16 pairs [tap][32ch][36]
__device__ __align__(16) __half   g_xT[BN*HW*CN];    // x transposed, channel-last f16 [b][h*w][c]

// ---------------- mma.sync m16n8k16 f16->f32 (base PTX, works on sm_103) ----------------
__device__ __forceinline__ void mma16816(float* d,
                                         uint32_t a0, uint32_t a1, uint32_t a2, uint32_t a3,
                                         uint32_t b0, uint32_t b1){
  asm volatile(
    "mma.sync.aligned.m16n8k16.row.col.f32.f16.f16.f32 "
    "{%0,%1,%2,%3}, {%4,%5,%6,%7}, {%8,%9}, {%0,%1,%2,%3};"
    : "+f"(d[0]), "+f"(d[1]), "+f"(d[2]), "+f"(d[3])
    : "r"(a0), "r"(a1), "r"(a2), "r"(a3), "r"(b0), "r"(b1));
}

// ---------------- kernel T+B fused: transpose x AND weight prep ----------------
__global__ __launch_bounds__(256)
void prep_all(const float* __restrict__ x,
              const float* __restrict__ weight,
              const float* __restrict__ offw,
              const float* __restrict__ modw){
  const int bx = blockIdx.x;
  if (bx < HN*BN){
    // ---- transpose x -> channel-last f16 (float4 loads) ----
    __shared__ uint32_t T[128*36];   // [px][36 u32]
    const int b  = bx >> 7;
    const int ho = bx & 127;
    const float* xr = x + b*CN*HW + ho*WN;

    for (int j = threadIdx.x; j < 32*32; j += 256){
      int cp = j >> 5;          // channel pair 0..31
      int q  = j & 31;          // px quad 0..31
      float4 v0 = *(const float4*)(xr + (2*cp    )*HW + q*4);
      float4 v1 = *(const float4*)(xr + (2*cp + 1)*HW + q*4);
      __half2 h0 = __floats2half2_rn(v0.x, v1.x);
      __half2 h1 = __floats2half2_rn(v0.y, v1.y);
      __half2 h2 = __floats2half2_rn(v0.z, v1.z);
      __half2 h3 = __floats2half2_rn(v0.w, v1.w);
      T[(q*4    )*36 + cp] = *(uint32_t*)&h0;
      T[(q*4 + 1)*36 + cp] = *(uint32_t*)&h1;
      T[(q*4 + 2)*36 + cp] = *(uint32_t*)&h2;
      T[(q*4 + 3)*36 + cp] = *(uint32_t*)&h3;
    }
    __syncthreads();

    float4* dst = (float4*)(g_xT + (b*HW + ho*WN)*CN);
    for (int j = threadIdx.x; j < 128*8; j += 256){
      int px = j >> 3, f4 = j & 7;
      dst[j] = *(float4*)&T[px*36 + f4*4];
    }
  } else {
    // ---- weight prep ----
    int i = (bx - HN*BN)*256 + threadIdx.x;
    if (i < K2C*ON*CN){
      int c = i & 63, o = (i >> 6) & 63, k = i >> 12;
      g_wh[i] = __float2half(weight[(o*CN + c)*K2C + k]);
    }
    if (i < K2C*32*32){
      int tap = i >> 10;
      int rem = i & 1023;
      int ch  = rem >> 5;
      int cp  = rem & 31;
      float v0 = 0.f, v1 = 0.f;
      int c0 = cp*2, c1 = cp*2 + 1;
      if (ch < 18){
        v0 = offw[ch*CK + c0*9 + tap];
        v1 = offw[ch*CK + c1*9 + tap];
      } else if (ch < 27){
        v0 = modw[(ch-18)*CK + c0*9 + tap];
        v1 = modw[(ch-18)*CK + c1*9 + tap];
      }
      __half2 h2 = __floats2half2_rn(v0, v1);
      g_wsA[(tap*32 + ch)*36 + cp] = *(uint32_t*)&h2;
    }
    if (i < K2C*32*4){
      int row = i >> 2, cp = 32 + (i & 3);
      g_wsA[row*36 + cp] = 0u;
    }
  }
}

// ---------------- kernel A: offset + modulation conv via HMMA (unchanged) ----------------
#define XSP 72
#define XS_HALVES (3*130*XSP)            // 28080
#define WS_U32   (K2C*32*36)             // 10368
#define OSM_BYTES (XS_HALVES*2 + WS_U32*4)   // 97632 B

__device__ __forceinline__ void write_pix(int b, int ho, int wo,
                                          const float* __restrict__ offb,
                                          const float* __restrict__ modb,
                                          const float (&rr)[28]){
  float msum = 0.f;
  #pragma unroll
  for (int k = 0; k < 9; k++){
    float kyf = (float)(k/3) - 1.f;
    float kxf = (float)(k%3) - 1.f;
    int idx = ((b*9 + k)*HN + ho)*WN + wo;
    g_sy[idx] = (float)ho + kyf + rr[k]     + offb[k];
    g_sx[idx] = (float)wo + kxf + rr[9 + k] + offb[9 + k];
    float z = rr[18 + k] + modb[k];
    msum += 1.f / (1.f + expf(-z));
  }
  g_mm[(b*HN + ho)*WN + wo] = msum * (1.f/9.f);
}

__global__ __launch_bounds__(256, 2)
void offset_mma(const float* __restrict__ offb,
                const float* __restrict__ modb){
  extern __shared__ char osm[];
  __half*   Xs  = (__half*)osm;                    // [3*130][72]
  uint32_t* Ws  = (uint32_t*)(osm + XS_HALVES*2);  // [288][36]
  float*    Dsm = (float*)osm;                     // [128][33] (aliases Xs after sync)

  const int tid  = threadIdx.x;
  const int lane = tid & 31;
  const int wp   = tid >> 5;
  const int g    = lane >> 2;
  const int tg   = lane & 3;
  const int b    = blockIdx.y;
  const int ho   = blockIdx.x;

  {
    const float4* src = (const float4*)g_wsA;
    float4* dst = (float4*)Ws;
    for (int i = tid; i < WS_U32/4; i += 256) dst[i] = src[i];
  }

  {
    const int f4 = tid & 7;
    const uint4 zero4 = make_uint4(0,0,0,0);
    const __half* xtb = g_xT + b*HW*CN;
    for (int pos = tid >> 3; pos < 390; pos += 32){
      int r    = (pos >= 260) ? 2 : (pos >= 130 ? 1 : 0);
      int px_i = pos - r*130;
      int row  = ho - 1 + r;
      int wo   = px_i - 1;
      bool ok  = (row >= 0) && (row < HN) && (wo >= 0) && (wo < WN);
      uint4 v = ok ? *(const uint4*)(xtb + (row*WN + wo)*CN + f4*8) : zero4;
      *(uint4*)(Xs + pos*XSP + f4*8) = v;
    }
  }
  __syncthreads();

  float acc[4][4];
  #pragma unroll
  for (int nt = 0; nt < 4; nt++)
    #pragma unroll
    for (int j = 0; j < 4; j++) acc[nt][j] = 0.f;

  #pragma unroll
  for (int t = 0; t < 9; t++){
    const int ky = t / 3, kx = t % 3;
    const __half* Ar0 = Xs + (ky*130 + wp*16 + g + kx)*XSP;
    const __half* Ar1 = Ar0 + 8*XSP;
    const uint32_t* Wt = Ws + (t*32)*36;
    #pragma unroll
    for (int kt = 0; kt < 4; kt++){
      const int k0 = kt*16 + tg*2;
      uint32_t a0 = *(const uint32_t*)(Ar0 + k0);
      uint32_t a1 = *(const uint32_t*)(Ar1 + k0);
      uint32_t a2 = *(const uint32_t*)(Ar0 + k0 + 8);
      uint32_t a3 = *(const uint32_t*)(Ar1 + k0 + 8);
      #pragma unroll
      for (int nt = 0; nt < 4; nt++){
        const uint32_t* Wr = Wt + (nt*8 + g)*36 + (k0 >> 1);
        uint32_t b0 = Wr[0];
        uint32_t b1 = Wr[4];
        mma16816(acc[nt], a0, a1, a2, a3, b0, b1);
      }
    }
  }
  __syncthreads();

  {
    const int px0 = wp*16 + g;
    const int px1 = px0 + 8;
    #pragma unroll
    for (int nt = 0; nt < 4; nt++){
      int ch = nt*8 + tg*2;
      Dsm[px0*33 + ch]     = acc[nt][0];
      Dsm[px0*33 + ch + 1] = acc[nt][1];
      Dsm[px1*33 + ch]     = acc[nt][2];
      Dsm[px1*33 + ch + 1] = acc[nt][3];
    }
  }
  __syncthreads();

  if (tid < 128){
    float rr[28];
    #pragma unroll
    for (int j = 0; j < 28; j++) rr[j] = Dsm[tid*33 + j];
    write_pix(b, ho, tid, offb, modb, rr);
  }
}

// ---------------- kernel C: half-row CTA (64px), 128 threads, 4 CTAs/SM ----------------
#define APAD 72
#define DPX 64
#define ASZ (DPX*APAD)      // halves per A buffer
#define WSZ (ON*APAD)       // halves per W buffer
#define DSM2 ((2*ASZ + 2*WSZ)*2)   // 36864 bytes

__device__ __forceinline__ void sample_tap(int b, int t, int ho, int wo0, int wp, int pxo,
                                           const __half* __restrict__ xtb, int co,
                                           __half* __restrict__ An){
  #pragma unroll
  for (int it = 0; it < 4; it++){
    const int px = wp*16 + it*4 + pxo;      // local 0..63
    const int sidx = ((b*9 + t)*HN + ho)*WN + wo0 + px;
    float sy = g_sy[sidx], sx = g_sx[sidx];
    float y0f = floorf(sy), x0f = floorf(sx);
    float wy1 = sy - y0f, wx1 = sx - x0f;
    float wy0 = 1.f - wy1, wx0 = 1.f - wx1;
    int y0 = (int)y0f, x0i = (int)x0f;
    int y1 = y0 + 1,  x1i = x0i + 1;
    float my0 = (y0  >= 0 && y0  < HN) ? 1.f : 0.f;
    float my1 = (y1  >= 0 && y1  < HN) ? 1.f : 0.f;
    float mx0 = (x0i >= 0 && x0i < WN) ? 1.f : 0.f;
    float mx1 = (x1i >= 0 && x1i < WN) ? 1.f : 0.f;
    int cy0 = min(max(y0, 0), HN-1),  cy1 = min(max(y1, 0), HN-1);
    int cx0 = min(max(x0i, 0), WN-1), cx1 = min(max(x1i, 0), WN-1);
    __half2 W00 = __float2half2_rn(wy0*wx0*my0*mx0);
    __half2 W01 = __float2half2_rn(wy0*wx1*my0*mx1);
    __half2 W10 = __float2half2_rn(wy1*wx0*my1*mx0);
    __half2 W11 = __float2half2_rn(wy1*wx1*my1*mx1);

    uint4 c00 = *(const uint4*)(xtb + (cy0*WN + cx0)*CN + co);
    uint4 c01 = *(const uint4*)(xtb + (cy0*WN + cx1)*CN + co);
    uint4 c10 = *(const uint4*)(xtb + (cy1*WN + cx0)*CN + co);
    uint4 c11 = *(const uint4*)(xtb + (cy1*WN + cx1)*CN + co);

    const __half2* h00 = (const __half2*)&c00;
    const __half2* h01 = (const __half2*)&c01;
    const __half2* h10 = (const __half2*)&c10;
    const __half2* h11 = (const __half2*)&c11;
    __half2 s[4];
    #pragma unroll
    for (int j = 0; j < 4; j++){
      __half2 a = __hmul2(W00, h00[j]);
      a = __hfma2(W01, h01[j], a);
      a = __hfma2(W10, h10[j], a);
      a = __hfma2(W11, h11[j], a);
      s[j] = a;
    }
    *(uint4*)&An[px*APAD + co] = *(uint4*)s;
  }
}

__global__ __launch_bounds__(128, 4)
void deform_mma(const float* __restrict__ bias,
                float* __restrict__ out){
  extern __shared__ __half dsm2[];
  __half* Asm = dsm2;            // [2][64][APAD]
  __half* Wsm = dsm2 + 2*ASZ;    // [2][64][APAD]

  const int tid   = threadIdx.x;      // 0..127
  const int lane  = tid & 31;
  const int wp    = tid >> 5;         // 0..3
  const int g     = lane >> 2;
  const int tg    = lane & 3;
  const int pxo   = lane >> 3;
  const int chunk = lane & 7;
  const int wo0   = blockIdx.x * DPX; // 0 or 64
  const int ho    = blockIdx.y;
  const int b     = blockIdx.z;
  const __half* xtb = g_xT + b*HW*CN;
  const int co = chunk*8;

  float acc[8][4];
  #pragma unroll
  for (int nt = 0; nt < 8; nt++)
    #pragma unroll
    for (int j = 0; j < 4; j++) acc[nt][j] = 0.f;

  // ---- prologue: tap 0 into buffer 0 ----
  {
    const uint32_t* src = (const uint32_t*)g_wh;
    uint32_t* dst = (uint32_t*)Wsm;
    #pragma unroll
    for (int r = 0; r < 16; r++){
      int j = tid + r*128;
      dst[(j >> 5)*(APAD/2) + (j & 31)] = src[j];
    }
    sample_tap(b, 0, ho, wo0, wp, pxo, xtb, co, Asm);
  }
  __syncthreads();

  // ---- taps: stage W(t+1) + sample(t+1) into nxt, HMMA on cur, ONE sync ----
  for (int t = 0; t < 9; t++){
    const int cur = t & 1;
    const __half* Ac = Asm + cur*ASZ;
    const __half* Wc = Wsm + cur*WSZ;

    if (t < 8){
      __half* An = Asm + (cur^1)*ASZ;
      uint32_t* Wn = (uint32_t*)(Wsm + (cur^1)*WSZ);
      const uint32_t* src = (const uint32_t*)(g_wh + (t+1)*ON*CN);
      #pragma unroll
      for (int r = 0; r < 16; r++){
        int j = tid + r*128;
        Wn[(j >> 5)*(APAD/2) + (j & 31)] = src[j];
      }
      sample_tap(b, t+1, ho, wo0, wp, pxo, xtb, co, An);
    }

    // HMMA: warp m16 x n64 x k64 on cur
    const __half* Ar0 = Ac + (wp*16 + g)*APAD;
    const __half* Ar1 = Ar0 + 8*APAD;
    #pragma unroll
    for (int kt = 0; kt < 4; kt++){
      const int k0 = kt*16 + tg*2;
      uint32_t a0 = *(const uint32_t*)(Ar0 + k0);
      uint32_t a1 = *(const uint32_t*)(Ar1 + k0);
      uint32_t a2 = *(const uint32_t*)(Ar0 + k0 + 8);
      uint32_t a3 = *(const uint32_t*)(Ar1 + k0 + 8);
      #pragma unroll
      for (int nt = 0; nt < 8; nt++){
        const __half* Wr = Wc + (nt*8 + g)*APAD + k0;
        uint32_t b0 = *(const uint32_t*)(Wr);
        uint32_t b1 = *(const uint32_t*)(Wr + 8);
        mma16816(acc[nt], a0, a1, a2, a3, b0, b1);
      }
    }
    __syncthreads();
  }

  // ---- epilogue: * mod_mean + bias ----
  const int px0 = wp*16 + g;
  const int px1 = px0 + 8;
  const float mm0 = g_mm[(b*HN + ho)*WN + wo0 + px0];
  const float mm1 = g_mm[(b*HN + ho)*WN + wo0 + px1];
  #pragma unroll
  for (int nt = 0; nt < 8; nt++){
    int o0 = nt*8 + tg*2;
    float b0 = bias[o0], b1 = bias[o0 + 1];
    float* o0p = out + ((b*ON + o0    )*HN + ho)*WN + wo0;
    float* o1p = out + ((b*ON + o0 + 1)*HN + ho)*WN + wo0;
    o0p[px0] = acc[nt][0]*mm0 + b0;
    o1p[px0] = acc[nt][1]*mm0 + b1;
    o0p[px1] = acc[nt][2]*mm1 + b0;
    o1p[px1] = acc[nt][3]*mm1 + b1;
  }
}

// ---------------- launch ----------------
extern "C" void kernel_launch(void* const* d_in, const int* in_sizes, int n_in,
                              void* d_out, int out_size) {
  const float* x      = (const float*)d_in[0];
  const float* weight = (const float*)d_in[1];
  const float* bias   = (const float*)d_in[2];
  const float* offw   = (const float*)d_in[3];
  const float* offb   = (const float*)d_in[4];
  const float* modw   = (const float*)d_in[5];
  const float* modb   = (const float*)d_in[6];
  float* out = (float*)d_out;

  cudaFuncSetAttribute(offset_mma, cudaFuncAttributeMaxDynamicSharedMemorySize, OSM_BYTES);
  cudaFuncSetAttribute(deform_mma, cudaFuncAttributeMaxDynamicSharedMemorySize, DSM2);

  prep_all<<<HN*BN + 144, 256>>>(x, weight, offw, modw);
  offset_mma<<<dim3(HN, BN), 256, OSM_BYTES>>>(offb, modb);
  deform_mma<<<dim3(2, HN, BN), 128, DSM2>>>(bias, out);
}